// round 2
// baseline (speedup 1.0000x reference)
#include <cuda_runtime.h>
#include <cuda_fp16.h>

// x:   (B=4, 3, H=2048, W=2048) fp32
// LUT: (3, 33, 33, 33) fp32, index = c*33^3 + b*1089 + g*33 + r
#define NPTS     35937          // 33^3
#define ROW      33
#define PLANE    1089           // 33*33
#define SLAB_PLANES 17          // b-planes per slab (0..16 / 16..32)
#define SLAB_PTS (SLAB_PLANES * PLANE)   // 18513
#define HW       4194304        // 2048*2048
#define NPIX     16777216       // 4 * HW (pixels per channel-plane set)
#define THREADS  1024
#define BLOCKS   152
// smem: RGP (uint2 = {half2 rg[i], half2 rg[i+1]}) + BP (half2 {b[i], b[i+1]})
#define RGP_BYTES (SLAB_PTS * 8)
#define BP_BYTES  (SLAB_PTS * 4)
#define SMEM_BYTES (RGP_BYTES + BP_BYTES)

extern __shared__ unsigned char smem_raw[];

__device__ __forceinline__ float lerpf(float a, float b, float f) {
    return fmaf(f, b - a, a);
}

__global__ void __launch_bounds__(THREADS, 1)
lut3d_slab_kernel(const float* __restrict__ x, const float* __restrict__ LUT,
                  float* __restrict__ out) {
    uint2*   RGP = (uint2*)smem_raw;                       // rg pairs, 8B/pt
    __half2* BP  = (__half2*)(smem_raw + RGP_BYTES);       // b  pairs, 4B/pt

    const int slab      = blockIdx.x & 1;          // 0: b-planes 0..16, 1: 16..32
    const int slab_base = slab ? 16 : 0;
    const int goff      = slab_base * PLANE;       // global lattice offset

    // Build pair tables for this slab: entry i covers lattice points (i, i+1).
    for (int li = threadIdx.x; li < SLAB_PTS; li += THREADS) {
        int gi = goff + li;
        int gn = (gi + 1 < NPTS) ? gi + 1 : gi;    // clamp only the very last pt
        float r0v = __ldg(&LUT[gi]);
        float g0v = __ldg(&LUT[NPTS + gi]);
        float b0v = __ldg(&LUT[2 * NPTS + gi]);
        float r1v = __ldg(&LUT[gn]);
        float g1v = __ldg(&LUT[NPTS + gn]);
        float b1v = __ldg(&LUT[2 * NPTS + gn]);
        __half2 lo = __floats2half2_rn(r0v, g0v);
        __half2 hi = __floats2half2_rn(r1v, g1v);
        uint2 e;
        e.x = *(unsigned int*)&lo;
        e.y = *(unsigned int*)&hi;
        RGP[li] = e;
        BP[li]  = __floats2half2_rn(b0v, b1v);
    }
    __syncthreads();

    const int group  = blockIdx.x >> 1;            // 0..75 within slab group
    const int stride = (BLOCKS / 2) * THREADS;     // 76 * 1024

    for (int q = group * THREADS + threadIdx.x; q < NPIX; q += stride) {
        int img  = q >> 22;                        // q / HW
        int p    = q & (HW - 1);
        int base = img * (3 * HW) + p;

        float pr = x[base];
        float pg = x[base + HW];
        float pb = x[base + 2 * HW];

        float rr = pr * 32.0f;
        float gg = pg * 32.0f;
        float bb = pb * 32.0f;
        int r0 = min(max(__float2int_rd(rr), 0), 31);
        int g0 = min(max(__float2int_rd(gg), 0), 31);
        int b0 = min(max(__float2int_rd(bb), 0), 31);

        bool active = slab ? (b0 >= 16) : (b0 < 16);
        if (active) {
            float fr = rr - (float)r0;
            float fg = gg - (float)g0;
            float fb = bb - (float)b0;

            int lbase = (b0 - slab_base) * PLANE + g0 * ROW + r0;

            // 4 r-pairs: (g0,b0) (g0+1,b0) (g0,b0+1) (g0+1,b0+1)
            int i00 = lbase;
            int i10 = lbase + ROW;
            int i01 = lbase + PLANE;
            int i11 = lbase + PLANE + ROW;

            uint2 e00 = RGP[i00];
            uint2 e10 = RGP[i10];
            uint2 e01 = RGP[i01];
            uint2 e11 = RGP[i11];
            __half2 b00 = BP[i00];
            __half2 b10 = BP[i10];
            __half2 b01 = BP[i01];
            __half2 b11 = BP[i11];

            float2 lo00 = __half22float2(*(__half2*)&e00.x);
            float2 hi00 = __half22float2(*(__half2*)&e00.y);
            float2 lo10 = __half22float2(*(__half2*)&e10.x);
            float2 hi10 = __half22float2(*(__half2*)&e10.y);
            float2 lo01 = __half22float2(*(__half2*)&e01.x);
            float2 hi01 = __half22float2(*(__half2*)&e01.y);
            float2 lo11 = __half22float2(*(__half2*)&e11.x);
            float2 hi11 = __half22float2(*(__half2*)&e11.y);
            float2 fb00 = __half22float2(b00);
            float2 fb10 = __half22float2(b10);
            float2 fb01 = __half22float2(b01);
            float2 fb11 = __half22float2(b11);

            // r-lerp per pair
            float r00 = lerpf(lo00.x, hi00.x, fr);
            float g00v = lerpf(lo00.y, hi00.y, fr);
            float bv00 = lerpf(fb00.x, fb00.y, fr);
            float r10 = lerpf(lo10.x, hi10.x, fr);
            float g10v = lerpf(lo10.y, hi10.y, fr);
            float bv10 = lerpf(fb10.x, fb10.y, fr);
            float r01 = lerpf(lo01.x, hi01.x, fr);
            float g01v = lerpf(lo01.y, hi01.y, fr);
            float bv01 = lerpf(fb01.x, fb01.y, fr);
            float r11 = lerpf(lo11.x, hi11.x, fr);
            float g11v = lerpf(lo11.y, hi11.y, fr);
            float bv11 = lerpf(fb11.x, fb11.y, fr);

            // g-lerp
            float r0g = lerpf(r00, r10, fg);
            float g0g = lerpf(g00v, g10v, fg);
            float b0g = lerpf(bv00, bv10, fg);
            float r1g = lerpf(r01, r11, fg);
            float g1g = lerpf(g01v, g11v, fg);
            float b1g = lerpf(bv01, bv11, fg);

            // b-lerp
            out[base]          = lerpf(r0g, r1g, fb);
            out[base + HW]     = lerpf(g0g, g1g, fb);
            out[base + 2 * HW] = lerpf(b0g, b1g, fb);
        }
    }
}

extern "C" void kernel_launch(void* const* d_in, const int* in_sizes, int n_in,
                              void* d_out, int out_size) {
    const float* x   = (const float*)d_in[0];
    const float* LUT = (const float*)d_in[1];
    float* out = (float*)d_out;

    cudaFuncSetAttribute(lut3d_slab_kernel,
                         cudaFuncAttributeMaxDynamicSharedMemorySize, SMEM_BYTES);
    lut3d_slab_kernel<<<BLOCKS, THREADS, SMEM_BYTES>>>(x, LUT, out);
}

// round 4
// speedup vs baseline: 1.4743x; 1.4743x over previous
#include <cuda_runtime.h>
#include <cuda_fp16.h>

// x:   (B=4, 3, H=2048, W=2048) fp32
// LUT: (3, 33, 33, 33) fp32, index = c*33^3 + b*1089 + g*33 + r
#define NPTS   35937            // 33^3
#define HW     4194304          // 2048*2048 (plane size)
#define HW4    1048576          // HW/4  (= 2^20)
#define NVEC   4194304          // B*HW/4 total float4 pixel-vecs
#define THREADS 1024            // 32 warps/SM (R1 had 16) — hide LDS latency
#define BLOCKS  152             // one block per SM (GB300 = 152 SMs), 1 wave
#define SMEM_BYTES (NPTS * 4 + NPTS * 2 + 16)   // half2 rg table + half b table

struct F3 { float x, y, z; };

__device__ __forceinline__ F3 lerp3(F3 a, F3 b, float f) {
    F3 r;
    r.x = fmaf(f, b.x - a.x, a.x);
    r.y = fmaf(f, b.y - a.y, a.y);
    r.z = fmaf(f, b.z - a.z, a.z);
    return r;
}

__device__ __forceinline__ F3 load3(const __half2* __restrict__ srg,
                                    const __half*  __restrict__ sb, int i) {
    float2 rg = __half22float2(srg[i]);
    F3 v;
    v.x = rg.x;
    v.y = rg.y;
    v.z = __half2float(sb[i]);
    return v;
}

__device__ __forceinline__ void lut_px(float r, float g, float b,
                                       const __half2* __restrict__ srg,
                                       const __half*  __restrict__ sb,
                                       float& outr, float& outg, float& outb) {
    float rr = r * 32.0f;
    float gg = g * 32.0f;
    float bb = b * 32.0f;
    int r0 = __float2int_rd(rr);
    int g0 = __float2int_rd(gg);
    int b0 = __float2int_rd(bb);
    r0 = min(max(r0, 0), 31);
    g0 = min(max(g0, 0), 31);
    b0 = min(max(b0, 0), 31);
    float fr = rr - (float)r0;
    float fg = gg - (float)g0;
    float fb = bb - (float)b0;

    int i000 = b0 * 1089 + g0 * 33 + r0;
    int i010 = i000 + 33;
    int i100 = i000 + 1089;
    int i110 = i100 + 33;

    F3 v000 = load3(srg, sb, i000);
    F3 v001 = load3(srg, sb, i000 + 1);
    F3 v010 = load3(srg, sb, i010);
    F3 v011 = load3(srg, sb, i010 + 1);
    F3 v100 = load3(srg, sb, i100);
    F3 v101 = load3(srg, sb, i100 + 1);
    F3 v110 = load3(srg, sb, i110);
    F3 v111 = load3(srg, sb, i110 + 1);

    F3 c00 = lerp3(v000, v001, fr);
    F3 c01 = lerp3(v010, v011, fr);
    F3 c10 = lerp3(v100, v101, fr);
    F3 c11 = lerp3(v110, v111, fr);
    F3 c0  = lerp3(c00, c01, fg);
    F3 c1  = lerp3(c10, c11, fg);
    F3 c   = lerp3(c0, c1, fb);

    outr = c.x;
    outg = c.y;
    outb = c.z;
}

extern __shared__ unsigned char smem_raw[];

__global__ void __launch_bounds__(THREADS, 1)
lut3d_kernel(const float* __restrict__ x, const float* __restrict__ LUT,
             float* __restrict__ out) {
    __half2* srg = (__half2*)smem_raw;
    __half*  sb  = (__half*)(smem_raw + (size_t)NPTS * sizeof(__half2));

    // Cooperative fp32 -> fp16 LUT conversion into shared memory.
    for (int i = threadIdx.x; i < NPTS; i += THREADS) {
        float vr = __ldg(&LUT[i]);
        float vg = __ldg(&LUT[NPTS + i]);
        float vb = __ldg(&LUT[2 * NPTS + i]);
        srg[i] = __floats2half2_rn(vr, vg);
        sb[i]  = __float2half_rn(vb);
    }
    __syncthreads();

    const float4* __restrict__ x4 = (const float4*)x;
    float4* __restrict__ o4 = (float4*)out;

    const int stride = gridDim.x * blockDim.x;
    for (int v = blockIdx.x * blockDim.x + threadIdx.x; v < NVEC; v += stride) {
        int img  = v >> 20;            // v / HW4
        int iv   = v & (HW4 - 1);      // v % HW4
        int base = img * (3 * HW4) + iv;

        float4 pr = x4[base];
        float4 pg = x4[base + HW4];
        float4 pb = x4[base + 2 * HW4];

        float4 orr, org, orb;
        lut_px(pr.x, pg.x, pb.x, srg, sb, orr.x, org.x, orb.x);
        lut_px(pr.y, pg.y, pb.y, srg, sb, orr.y, org.y, orb.y);
        lut_px(pr.z, pg.z, pb.z, srg, sb, orr.z, org.z, orb.z);
        lut_px(pr.w, pg.w, pb.w, srg, sb, orr.w, org.w, orb.w);

        o4[base]           = orr;
        o4[base + HW4]     = org;
        o4[base + 2 * HW4] = orb;
    }
}

extern "C" void kernel_launch(void* const* d_in, const int* in_sizes, int n_in,
                              void* d_out, int out_size) {
    const float* x   = (const float*)d_in[0];
    const float* LUT = (const float*)d_in[1];
    float* out = (float*)d_out;

    cudaFuncSetAttribute(lut3d_kernel,
                         cudaFuncAttributeMaxDynamicSharedMemorySize, SMEM_BYTES);
    lut3d_kernel<<<BLOCKS, THREADS, SMEM_BYTES>>>(x, LUT, out);
}

// round 5
// speedup vs baseline: 2.4985x; 1.6948x over previous
#include <cuda_runtime.h>
#include <cuda_fp16.h>

// x:   (B=4, 3, H=2048, W=2048) fp32
// LUT: (3, 33, 33, 33) fp32, index = c*33^3 + b*1089 + g*33 + r
#define NPTS   35937            // 33^3
#define ROW    33
#define PLANE  1089
#define HW4    1048576          // 2048*2048/4
#define NVEC   4194304          // B*HW/4 float4 pixel-vecs per plane set
#define THREADS 1024
#define GROUPS  50              // blocks per channel group
#define BLOCKS  (3 * GROUPS)    // 150
#define SMEM_BYTES (NPTS * 4 + 16)   // half2 pair table for ONE channel

extern __shared__ unsigned char smem_raw[];

// Interpolate one pixel for ONE channel using the r-pair table.
__device__ __forceinline__ float lut_px_1ch(float r, float g, float b,
                                            const __half2* __restrict__ P) {
    float rr = r * 32.0f;
    float gg = g * 32.0f;
    float bb = b * 32.0f;
    int r0 = min(max(__float2int_rd(rr), 0), 31);
    int g0 = min(max(__float2int_rd(gg), 0), 31);
    int b0 = min(max(__float2int_rd(bb), 0), 31);
    float fr = rr - (float)r0;
    float fg = gg - (float)g0;
    float fb = bb - (float)b0;

    int i00 = b0 * PLANE + g0 * ROW + r0;   // (g0,   b0)
    int i10 = i00 + ROW;                    // (g0+1, b0)
    int i01 = i00 + PLANE;                  // (g0,   b0+1)
    int i11 = i01 + ROW;                    // (g0+1, b0+1)

    float2 p00 = __half22float2(P[i00]);
    float2 p10 = __half22float2(P[i10]);
    float2 p01 = __half22float2(P[i01]);
    float2 p11 = __half22float2(P[i11]);

    float v00 = fmaf(fr, p00.y - p00.x, p00.x);
    float v10 = fmaf(fr, p10.y - p10.x, p10.x);
    float v01 = fmaf(fr, p01.y - p01.x, p01.x);
    float v11 = fmaf(fr, p11.y - p11.x, p11.x);

    float v0 = fmaf(fg, v10 - v00, v00);
    float v1 = fmaf(fg, v11 - v01, v01);
    return fmaf(fb, v1 - v0, v0);
}

__global__ void __launch_bounds__(THREADS, 1)
lut3d_chsplit_kernel(const float* __restrict__ x, const float* __restrict__ LUT,
                     float* __restrict__ out) {
    __half2* P = (__half2*)smem_raw;

    const int c    = blockIdx.x % 3;        // output channel this block computes
    const int rank = blockIdx.x / 3;        // 0..GROUPS-1, identical across channels

    // Build this channel's r-pair table: P[i] = {LUT[c,i], LUT[c,i+1]} (fp16).
    const float* Lc = LUT + c * NPTS;
    for (int i = threadIdx.x; i < NPTS; i += THREADS) {
        float v0 = __ldg(&Lc[i]);
        int j = (i + 1 < NPTS) ? i + 1 : i;
        float v1 = __ldg(&Lc[j]);
        P[i] = __floats2half2_rn(v0, v1);
    }
    __syncthreads();

    const float4* __restrict__ x4 = (const float4*)x;
    float4* __restrict__ o4 = (float4*)out;

    const int stride = GROUPS * THREADS;    // same stride for every channel group
    for (int v = rank * THREADS + threadIdx.x; v < NVEC; v += stride) {
        int img  = v >> 20;                 // v / HW4
        int iv   = v & (HW4 - 1);           // v % HW4
        int base = img * (3 * HW4) + iv;    // float4 index of r-plane

        float4 pr = x4[base];
        float4 pg = x4[base + HW4];
        float4 pb = x4[base + 2 * HW4];

        float4 o;
        o.x = lut_px_1ch(pr.x, pg.x, pb.x, P);
        o.y = lut_px_1ch(pr.y, pg.y, pb.y, P);
        o.z = lut_px_1ch(pr.z, pg.z, pb.z, P);
        o.w = lut_px_1ch(pr.w, pg.w, pb.w, P);

        o4[base + c * HW4] = o;
    }
}

extern "C" void kernel_launch(void* const* d_in, const int* in_sizes, int n_in,
                              void* d_out, int out_size) {
    const float* x   = (const float*)d_in[0];
    const float* LUT = (const float*)d_in[1];
    float* out = (float*)d_out;

    cudaFuncSetAttribute(lut3d_chsplit_kernel,
                         cudaFuncAttributeMaxDynamicSharedMemorySize, SMEM_BYTES);
    lut3d_chsplit_kernel<<<BLOCKS, THREADS, SMEM_BYTES>>>(x, LUT, out);
}

// round 7
// speedup vs baseline: 2.6834x; 1.0740x over previous
#include <cuda_runtime.h>
#include <cuda_fp16.h>

// x:   (B=4, 3, H=2048, W=2048) fp32
// LUT: (3, 33, 33, 33) fp32, index = c*33^3 + b*1089 + g*33 + r
#define NPTS   35937            // 33^3
#define ROW    33
#define PLANE  1089
#define HW4    1048576          // 2048*2048/4
#define NVEC   4194304          // B*HW/4 float4 pixel-vecs per plane set
#define THREADS 1024
#define GROUPS  50              // blocks per channel group
#define BLOCKS  (3 * GROUPS)    // 150
#define SMEM_BYTES (NPTS * 4 + 16)   // half2 pair table for ONE channel

extern __shared__ unsigned char smem_raw[];

// Interpolate one pixel for ONE channel using the r-pair table.
__device__ __forceinline__ float lut_px_1ch(float r, float g, float b,
                                            const __half2* __restrict__ P) {
    float rr = r * 32.0f;
    float gg = g * 32.0f;
    float bb = b * 32.0f;
    int r0 = min(max(__float2int_rd(rr), 0), 31);
    int g0 = min(max(__float2int_rd(gg), 0), 31);
    int b0 = min(max(__float2int_rd(bb), 0), 31);
    float fr = rr - (float)r0;
    float fg = gg - (float)g0;
    float fb = bb - (float)b0;

    int i00 = b0 * PLANE + g0 * ROW + r0;   // (g0,   b0)
    int i10 = i00 + ROW;                    // (g0+1, b0)
    int i01 = i00 + PLANE;                  // (g0,   b0+1)
    int i11 = i01 + ROW;                    // (g0+1, b0+1)

    float2 p00 = __half22float2(P[i00]);
    float2 p10 = __half22float2(P[i10]);
    float2 p01 = __half22float2(P[i01]);
    float2 p11 = __half22float2(P[i11]);

    float v00 = fmaf(fr, p00.y - p00.x, p00.x);
    float v10 = fmaf(fr, p10.y - p10.x, p10.x);
    float v01 = fmaf(fr, p01.y - p01.x, p01.x);
    float v11 = fmaf(fr, p11.y - p11.x, p11.x);

    float v0 = fmaf(fg, v10 - v00, v00);
    float v1 = fmaf(fg, v11 - v01, v01);
    return fmaf(fb, v1 - v0, v0);
}

__global__ void __launch_bounds__(THREADS, 1)
lut3d_chsplit_kernel(const float* __restrict__ x, const float* __restrict__ LUT,
                     float* __restrict__ out) {
    __half2* P = (__half2*)smem_raw;

    const int c    = blockIdx.x % 3;        // output channel this block computes
    const int rank = blockIdx.x / 3;        // 0..GROUPS-1, identical across channels

    // Build this channel's r-pair table: P[i] = {LUT[c,i], LUT[c,i+1]} (fp16).
    // Scalar loads: LUT + c*NPTS is only 4-byte aligned for c=1,2, so no float4.
    const float* Lc = LUT + c * NPTS;
    for (int i = threadIdx.x; i < NPTS; i += THREADS) {
        float v0 = __ldg(&Lc[i]);
        int j = (i + 1 < NPTS) ? i + 1 : i;
        float v1 = __ldg(&Lc[j]);
        P[i] = __floats2half2_rn(v0, v1);
    }
    __syncthreads();

    const float4* __restrict__ x4 = (const float4*)x;
    float4* __restrict__ o4 = (float4*)out;

    const int stride = GROUPS * THREADS;    // same stride for every channel group

    int v = rank * THREADS + threadIdx.x;
    if (v >= NVEC) return;

    // Prologue: load first iteration's pixel vectors.
    int img  = v >> 20;
    int iv   = v & (HW4 - 1);
    int base = img * (3 * HW4) + iv;
    float4 pr = x4[base];
    float4 pg = x4[base + HW4];
    float4 pb = x4[base + 2 * HW4];

    while (true) {
        int vn = v + stride;
        bool more = (vn < NVEC);

        // Prefetch next iteration's x while current gathers run.
        int vc = more ? vn : v;
        int img_n  = vc >> 20;
        int iv_n   = vc & (HW4 - 1);
        int base_n = img_n * (3 * HW4) + iv_n;
        float4 nr = x4[base_n];
        float4 ng = x4[base_n + HW4];
        float4 nb = x4[base_n + 2 * HW4];

        float4 o;
        o.x = lut_px_1ch(pr.x, pg.x, pb.x, P);
        o.y = lut_px_1ch(pr.y, pg.y, pb.y, P);
        o.z = lut_px_1ch(pr.z, pg.z, pb.z, P);
        o.w = lut_px_1ch(pr.w, pg.w, pb.w, P);

        o4[base + c * HW4] = o;

        if (!more) break;
        v = vn;
        base = base_n;
        pr = nr; pg = ng; pb = nb;
    }
}

extern "C" void kernel_launch(void* const* d_in, const int* in_sizes, int n_in,
                              void* d_out, int out_size) {
    const float* x   = (const float*)d_in[0];
    const float* LUT = (const float*)d_in[1];
    float* out = (float*)d_out;

    cudaFuncSetAttribute(lut3d_chsplit_kernel,
                         cudaFuncAttributeMaxDynamicSharedMemorySize, SMEM_BYTES);
    lut3d_chsplit_kernel<<<BLOCKS, THREADS, SMEM_BYTES>>>(x, LUT, out);
}